// round 9
// baseline (speedup 1.0000x reference)
#include <cuda_runtime.h>
#include <math.h>

// Quincunx lattice max pooling, shapes fixed by the problem:
//   coset0, coset1: [B=4, C=32, H=512, W=512] fp32
//   out:            [2, B, C, H, W] fp32   (out0 then out1)
//
// out0[i,j] = max(c0[i,j], c0[i+1,j], c0[i,j+1], c0[i+1,j+1], c1[i,j])
// out1[i,j] = max(c1[i,j], c1[i+1,j], c1[i,j+1], c1[i+1,j+1], c0[i+1,j+1])
// OOB -> -inf (ignored).
//
// R8: R7 structure (4 output rows/thread, 5 input rows/coset, shuffle tails,
// lane-31 predicated scalar loads, __stwt write-through stores, block=512)
// + read cache-policy segregation:
//   - interior rows 4q+1..4q+3: read exactly once -> __ldcs (stream, evict-first)
//   - halo rows 4q, 4q+4: read by two adjacent quads + tails -> default (__ldg)
// Keeps L2 capacity for genuinely-reused lines.

#define HH   512
#define WW   512
#define W4   128          // float4 per row
#define QQ   128          // row quads per image
#define NEGINF __int_as_float(0xff800000)

__global__ void __launch_bounds__(512)
lattice_pool_kernel(const float4* __restrict__ c0,
                    const float4* __restrict__ c1,
                    float4* __restrict__ out0,
                    float4* __restrict__ out1,
                    int total)   // total threads = B*C*QQ*W4
{
    int idx = blockIdx.x * blockDim.x + threadIdx.x;
    if (idx >= total) return;

    int jv  = idx & (W4 - 1);           // float4 column
    int q   = (idx >> 7) & (QQ - 1);    // row-quad within image
    long img = idx >> 14;               // (b,c) plane index

    long base = img * (long)(HH * W4) + (long)(4 * q) * W4 + jv;
    bool last_quad = (q == QQ - 1);
    bool last_col  = (jv == W4 - 1);
    const float ni = NEGINF;
    const float4 ni4 = make_float4(ni, ni, ni, ni);

    // Five input rows per coset: 4q .. 4q+4
    // Halo rows (0 and 4): default policy (reused by neighbor quad).
    // Interior rows (1..3): streaming loads (single use).
    float4 a[5], b[5];
    a[0] = __ldg(&c0[base]);
    b[0] = __ldg(&c1[base]);
#pragma unroll
    for (int r = 1; r < 4; r++) {
        a[r] = __ldcs(&c0[base + r * W4]);
        b[r] = __ldcs(&c1[base + r * W4]);
    }
    a[4] = last_quad ? ni4 : __ldg(&c0[base + 4 * W4]);
    b[4] = last_quad ? ni4 : __ldg(&c1[base + 4 * W4]);

    // Horizontal tail (element at column 4*jv+4) via shuffle from lane+1.
    const unsigned m = 0xffffffffu;
    float an[5], bn[5];
#pragma unroll
    for (int r = 0; r < 5; r++) {
        an[r] = __shfl_down_sync(m, a[r].x, 1);
        bn[r] = __shfl_down_sync(m, b[r].x, 1);
    }

    int lane = threadIdx.x & 31;
    if (lane == 31) {
        if (!last_col) {
            const float* c0s = (const float*)c0;
            const float* c1s = (const float*)c1;
            long e = base * 4 + 4;      // scalar idx of col 4*jv+4, row 4q
#pragma unroll
            for (int r = 0; r < 4; r++) {
                an[r] = __ldg(c0s + e + r * WW);
                bn[r] = __ldg(c1s + e + r * WW);
            }
            if (!last_quad) {
                an[4] = __ldg(c0s + e + 4 * WW);
                bn[4] = __ldg(c1s + e + 4 * WW);
            } else {
                an[4] = ni; bn[4] = ni;
            }
        } else {
#pragma unroll
            for (int r = 0; r < 5; r++) { an[r] = ni; bn[r] = ni; }
        }
    }

    // Per output row r (global row 4q+r):
    //   out0: max over c0 rows (r, r+1) cols (j, j+1)  +  c1[r] same-site
    //   out1: max over c1 rows (r, r+1) cols (j, j+1)  +  c0[r+1] down-right
#pragma unroll
    for (int r = 0; r < 4; r++) {
        float4 o;
        // out0
        {
            float vx = fmaxf(a[r].x, a[r + 1].x);
            float vy = fmaxf(a[r].y, a[r + 1].y);
            float vz = fmaxf(a[r].z, a[r + 1].z);
            float vw = fmaxf(a[r].w, a[r + 1].w);
            float vn = fmaxf(an[r], an[r + 1]);
            o.x = fmaxf(fmaxf(vx, vy), b[r].x);
            o.y = fmaxf(fmaxf(vy, vz), b[r].y);
            o.z = fmaxf(fmaxf(vz, vw), b[r].z);
            o.w = fmaxf(fmaxf(vw, vn), b[r].w);
            __stwt(&out0[base + r * W4], o);
        }
        // out1
        {
            float vx = fmaxf(b[r].x, b[r + 1].x);
            float vy = fmaxf(b[r].y, b[r + 1].y);
            float vz = fmaxf(b[r].z, b[r + 1].z);
            float vw = fmaxf(b[r].w, b[r + 1].w);
            float vn = fmaxf(bn[r], bn[r + 1]);
            o.x = fmaxf(fmaxf(vx, vy), a[r + 1].y);
            o.y = fmaxf(fmaxf(vy, vz), a[r + 1].z);
            o.z = fmaxf(fmaxf(vz, vw), a[r + 1].w);
            o.w = fmaxf(fmaxf(vw, vn), an[r + 1]);
            __stwt(&out1[base + r * W4], o);
        }
    }
}

extern "C" void kernel_launch(void* const* d_in, const int* in_sizes, int n_in,
                              void* d_out, int out_size)
{
    const float4* c0 = (const float4*)d_in[0];
    const float4* c1 = (const float4*)d_in[1];
    int per_coset4 = in_sizes[0] / 4;          // float4 per coset
    int total = per_coset4 / 4;                // one thread per 4 output rows x 4 cols
    float4* out0 = (float4*)d_out;
    float4* out1 = out0 + per_coset4;

    int threads = 512;
    int blocks  = (total + threads - 1) / threads;
    lattice_pool_kernel<<<blocks, threads>>>(c0, c1, out0, out1, total);
}

// round 10
// speedup vs baseline: 1.0681x; 1.0681x over previous
#include <cuda_runtime.h>
#include <math.h>

// Quincunx lattice max pooling, shapes fixed by the problem:
//   coset0, coset1: [B=4, C=32, H=512, W=512] fp32
//   out:            [2, B, C, H, W] fp32   (out0 then out1)
//
// out0[i,j] = max(c0[i,j], c0[i+1,j], c0[i,j+1], c0[i+1,j+1], c1[i,j])
// out1[i,j] = max(c1[i,j], c1[i+1,j], c1[i,j+1], c1[i+1,j+1], c0[i+1,j+1])
// OOB -> -inf (ignored).
//
// R9: 2-row unit (R2 shape: ~40 regs, occ ~57%) + __stwt write-through
// stores (R7's winning store policy) + block=512. All reads default policy
// (R8 showed the tail loads reuse "interior" lines; evict-first hurt).

#define HH   512
#define WW   512
#define W4   128          // float4 per row
#define PP   256          // row pairs per image
#define NEGINF __int_as_float(0xff800000)

__global__ void __launch_bounds__(512)
lattice_pool_kernel(const float4* __restrict__ c0,
                    const float4* __restrict__ c1,
                    float4* __restrict__ out0,
                    float4* __restrict__ out1,
                    int total)   // total threads = B*C*PP*W4
{
    int idx = blockIdx.x * blockDim.x + threadIdx.x;
    if (idx >= total) return;

    int jv  = idx & (W4 - 1);           // float4 column
    int p   = (idx >> 7) & (PP - 1);    // row-pair within image
    long img = idx >> 15;               // (b,c) plane index

    long base = img * (long)(HH * W4) + (long)(2 * p) * W4 + jv;
    bool last_pair = (p == PP - 1);
    bool last_col  = (jv == W4 - 1);
    const float ni = NEGINF;
    const float4 ni4 = make_float4(ni, ni, ni, ni);

    // Three input rows per coset: 2p, 2p+1, 2p+2
    float4 a0 = c0[base];
    float4 a1 = c0[base + W4];
    float4 b0 = c1[base];
    float4 b1 = c1[base + W4];
    float4 a2 = last_pair ? ni4 : c0[base + 2 * W4];
    float4 b2 = last_pair ? ni4 : c1[base + 2 * W4];

    // Horizontal tail (element at column 4*jv+4) via shuffle from lane+1.
    const unsigned m = 0xffffffffu;
    float a0n = __shfl_down_sync(m, a0.x, 1);
    float a1n = __shfl_down_sync(m, a1.x, 1);
    float a2n = __shfl_down_sync(m, a2.x, 1);
    float b0n = __shfl_down_sync(m, b0.x, 1);
    float b1n = __shfl_down_sync(m, b1.x, 1);
    float b2n = __shfl_down_sync(m, b2.x, 1);

    int lane = threadIdx.x & 31;
    if (lane == 31) {
        if (!last_col) {
            const float* c0s = (const float*)c0;
            const float* c1s = (const float*)c1;
            long e = base * 4 + 4;      // scalar idx of col 4*jv+4, row 2p
            a0n = __ldg(c0s + e);
            a1n = __ldg(c0s + e + WW);
            b0n = __ldg(c1s + e);
            b1n = __ldg(c1s + e + WW);
            if (!last_pair) {
                a2n = __ldg(c0s + e + 2 * WW);
                b2n = __ldg(c1s + e + 2 * WW);
            } else {
                a2n = ni; b2n = ni;
            }
        } else {
            a0n = a1n = a2n = b0n = b1n = b2n = ni;
        }
    }

    float4 r;
    // out0 row 2p: c0 2x2 + c1 same-site
    {
        float vx = fmaxf(a0.x, a1.x), vy = fmaxf(a0.y, a1.y);
        float vz = fmaxf(a0.z, a1.z), vw = fmaxf(a0.w, a1.w);
        float vn = fmaxf(a0n, a1n);
        r.x = fmaxf(fmaxf(vx, vy), b0.x);
        r.y = fmaxf(fmaxf(vy, vz), b0.y);
        r.z = fmaxf(fmaxf(vz, vw), b0.z);
        r.w = fmaxf(fmaxf(vw, vn), b0.w);
        __stwt(&out0[base], r);
    }
    // out1 row 2p: c1 2x2 + c0 down-right diagonal
    {
        float vx = fmaxf(b0.x, b1.x), vy = fmaxf(b0.y, b1.y);
        float vz = fmaxf(b0.z, b1.z), vw = fmaxf(b0.w, b1.w);
        float vn = fmaxf(b0n, b1n);
        r.x = fmaxf(fmaxf(vx, vy), a1.y);
        r.y = fmaxf(fmaxf(vy, vz), a1.z);
        r.z = fmaxf(fmaxf(vz, vw), a1.w);
        r.w = fmaxf(fmaxf(vw, vn), a1n);
        __stwt(&out1[base], r);
    }
    // out0 row 2p+1: c0 rows (2p+1,2p+2) + c1 row 2p+1
    {
        float vx = fmaxf(a1.x, a2.x), vy = fmaxf(a1.y, a2.y);
        float vz = fmaxf(a1.z, a2.z), vw = fmaxf(a1.w, a2.w);
        float vn = fmaxf(a1n, a2n);
        r.x = fmaxf(fmaxf(vx, vy), b1.x);
        r.y = fmaxf(fmaxf(vy, vz), b1.y);
        r.z = fmaxf(fmaxf(vz, vw), b1.z);
        r.w = fmaxf(fmaxf(vw, vn), b1.w);
        __stwt(&out0[base + W4], r);
    }
    // out1 row 2p+1: c1 rows (2p+1,2p+2) + c0 row 2p+2 diagonal
    {
        float vx = fmaxf(b1.x, b2.x), vy = fmaxf(b1.y, b2.y);
        float vz = fmaxf(b1.z, b2.z), vw = fmaxf(b1.w, b2.w);
        float vn = fmaxf(b1n, b2n);
        r.x = fmaxf(fmaxf(vx, vy), a2.y);
        r.y = fmaxf(fmaxf(vy, vz), a2.z);
        r.z = fmaxf(fmaxf(vz, vw), a2.w);
        r.w = fmaxf(fmaxf(vw, vn), a2n);
        __stwt(&out1[base + W4], r);
    }
}

extern "C" void kernel_launch(void* const* d_in, const int* in_sizes, int n_in,
                              void* d_out, int out_size)
{
    const float4* c0 = (const float4*)d_in[0];
    const float4* c1 = (const float4*)d_in[1];
    int per_coset4 = in_sizes[0] / 4;          // float4 per coset
    int total = per_coset4 / 2;                // one thread per 2 output rows x 4 cols
    float4* out0 = (float4*)d_out;
    float4* out1 = out0 + per_coset4;

    int threads = 512;
    int blocks  = (total + threads - 1) / threads;
    lattice_pool_kernel<<<blocks, threads>>>(c0, c1, out0, out1, total);
}

// round 11
// speedup vs baseline: 1.0685x; 1.0004x over previous
#include <cuda_runtime.h>
#include <math.h>

// Quincunx lattice max pooling, shapes fixed by the problem:
//   coset0, coset1: [B=4, C=32, H=512, W=512] fp32
//   out:            [2, B, C, H, W] fp32   (out0 then out1)
//
// out0[i,j] = max(c0[i,j], c0[i+1,j], c0[i,j+1], c0[i+1,j+1], c1[i,j])
// out1[i,j] = max(c1[i,j], c1[i+1,j], c1[i,j+1], c1[i+1,j+1], c0[i+1,j+1])
// OOB -> -inf (ignored).
//
// R10: 1-row unit (max occupancy, ~30 regs) + shuffle horizontal tails
// (lane-31 predicated scalar loads only) + __stwt write-through stores.
// Each input row is read by two vertical neighbors: second read is an L2
// hit, DRAM bytes unchanged; higher warp count densifies the DRAM request
// stream.

#define HH   512
#define WW   512
#define W4   128          // float4 per row
#define NEGINF __int_as_float(0xff800000)

__global__ void __launch_bounds__(256)
lattice_pool_kernel(const float4* __restrict__ c0,
                    const float4* __restrict__ c1,
                    float4* __restrict__ out0,
                    float4* __restrict__ out1,
                    int total)   // total threads = B*C*HH*W4
{
    int idx = blockIdx.x * blockDim.x + threadIdx.x;
    if (idx >= total) return;

    int jv = idx & (W4 - 1);          // float4 column
    int i  = (idx >> 7) & (HH - 1);   // row within image
    bool last_row = (i == HH - 1);
    bool last_col = (jv == W4 - 1);
    const float ni = NEGINF;
    const float4 ni4 = make_float4(ni, ni, ni, ni);

    // Rows i and i+1 of both cosets
    float4 a0 = c0[idx];
    float4 b0 = c1[idx];
    float4 a1 = last_row ? ni4 : c0[idx + W4];
    float4 b1 = last_row ? ni4 : c1[idx + W4];

    // Horizontal tail (column 4*jv+4) via shuffle from lane+1.
    const unsigned m = 0xffffffffu;
    float a0n = __shfl_down_sync(m, a0.x, 1);
    float a1n = __shfl_down_sync(m, a1.x, 1);
    float b0n = __shfl_down_sync(m, b0.x, 1);
    float b1n = __shfl_down_sync(m, b1.x, 1);

    int lane = threadIdx.x & 31;
    if (lane == 31) {
        if (!last_col) {
            const float* c0s = (const float*)c0;
            const float* c1s = (const float*)c1;
            long e = (long)idx * 4 + 4;
            a0n = __ldg(c0s + e);
            b0n = __ldg(c1s + e);
            if (!last_row) {
                a1n = __ldg(c0s + e + WW);
                b1n = __ldg(c1s + e + WW);
            } else {
                a1n = ni; b1n = ni;
            }
        } else {
            a0n = a1n = b0n = b1n = ni;
        }
    }

    float4 r;
    // out0: c0 2x2 window + c1 same-site
    {
        float vx = fmaxf(a0.x, a1.x), vy = fmaxf(a0.y, a1.y);
        float vz = fmaxf(a0.z, a1.z), vw = fmaxf(a0.w, a1.w);
        float vn = fmaxf(a0n, a1n);
        r.x = fmaxf(fmaxf(vx, vy), b0.x);
        r.y = fmaxf(fmaxf(vy, vz), b0.y);
        r.z = fmaxf(fmaxf(vz, vw), b0.z);
        r.w = fmaxf(fmaxf(vw, vn), b0.w);
        __stwt(&out0[idx], r);
    }
    // out1: c1 2x2 window + c0 down-right diagonal
    {
        float vx = fmaxf(b0.x, b1.x), vy = fmaxf(b0.y, b1.y);
        float vz = fmaxf(b0.z, b1.z), vw = fmaxf(b0.w, b1.w);
        float vn = fmaxf(b0n, b1n);
        r.x = fmaxf(fmaxf(vx, vy), a1.y);
        r.y = fmaxf(fmaxf(vy, vz), a1.z);
        r.z = fmaxf(fmaxf(vz, vw), a1.w);
        r.w = fmaxf(fmaxf(vw, vn), a1n);
        __stwt(&out1[idx], r);
    }
}

extern "C" void kernel_launch(void* const* d_in, const int* in_sizes, int n_in,
                              void* d_out, int out_size)
{
    const float4* c0 = (const float4*)d_in[0];
    const float4* c1 = (const float4*)d_in[1];
    int total = in_sizes[0] / 4;               // one thread per output row x 4 cols
    float4* out0 = (float4*)d_out;
    float4* out1 = out0 + total;

    int threads = 256;
    int blocks  = (total + threads - 1) / threads;
    lattice_pool_kernel<<<blocks, threads>>>(c0, c1, out0, out1, total);
}